// round 5
// baseline (speedup 1.0000x reference)
#include <cuda_runtime.h>
#include <math.h>

#define NN 150000
#define EE 2400000
#define BB 16384
#define N_USERS 100000
#define EMB 64
#define HID 128
#define LN_EPS 1e-5f
#define NBLKS 147   // ceil(NN/1024)

// ---------------- static scratch ----------------
__device__ float d_xs [(size_t)NN * 64];    // dinv[n] * x[n]
__device__ float d_h1 [(size_t)NN * 128];   // relu((A_hat x) W1 + b1)
__device__ float d_xs2[(size_t)NN * 64];    // dinv[n] * (h1 @ W2)[n]
__device__ int   d_counts[NN];
__device__ int   d_rowstart[NN];
__device__ int   d_cursor[NN];
__device__ float d_dinv[NN];
__device__ int   d_csrsrc[EE];
__device__ int   d_bsum[256];

// ---------------- CSR build ----------------
__global__ void k_zero_counts() {
    int i = blockIdx.x * blockDim.x + threadIdx.x;
    if (i < NN) d_counts[i] = 0;
}

__global__ void k_count(const int* __restrict__ dst) {
    int e = blockIdx.x * blockDim.x + threadIdx.x;
    if (e < EE) atomicAdd(&d_counts[dst[e]], 1);
}

__global__ void k_scan1() {
    __shared__ int s[1024];
    int t = threadIdx.x;
    int i = blockIdx.x * 1024 + t;
    int v = (i < NN) ? d_counts[i] : 0;
    s[t] = v;
    __syncthreads();
    for (int off = 1; off < 1024; off <<= 1) {
        int add = (t >= off) ? s[t - off] : 0;
        __syncthreads();
        s[t] += add;
        __syncthreads();
    }
    if (i < NN) d_rowstart[i] = s[t] - v;
    if (t == 1023) d_bsum[blockIdx.x] = s[1023];   // block total
}

// scan3: adds cross-block prefix (computed inline by warp 0) + finalize
__global__ void k_scan3() {
    __shared__ int pref;
    int b = blockIdx.x, t = threadIdx.x;
    if (t < 32) {
        int s = 0;
        for (int j = t; j < b; j += 32) s += d_bsum[j];
        #pragma unroll
        for (int o = 16; o; o >>= 1)
            s += __shfl_xor_sync(0xffffffffu, s, o);
        if (t == 0) pref = s;
    }
    __syncthreads();
    int i = b * 1024 + t;
    if (i < NN) {
        int rs = d_rowstart[i] + pref;
        d_rowstart[i] = rs;
        d_cursor[i]   = rs;
        d_dinv[i]     = rsqrtf(1.0f + (float)d_counts[i]);
    }
}

__global__ void k_fill(const int* __restrict__ src, const int* __restrict__ dst) {
    int e = blockIdx.x * blockDim.x + threadIdx.x;
    if (e < EE) {
        int d = dst[e];
        int p = atomicAdd(&d_cursor[d], 1);
        d_csrsrc[p] = src[e];
    }
}

// ---------------- prescale: xs = dinv[n] * x[n] ----------------
__global__ void k_prescale(const float* __restrict__ x) {
    int i = blockIdx.x * blockDim.x + threadIdx.x;     // float4 index
    if (i < NN * 16) {
        float4 v = ((const float4*)x)[i];
        float di = d_dinv[i >> 4];
        ((float4*)d_xs)[i] = make_float4(v.x * di, v.y * di, v.z * di, v.w * di);
    }
}

// ------ fused layer-1 aggregation + GEMM1: h1 = relu((A_hat x) W1 + b1) ------
// Block handles 32 nodes. Phase 1: 4 warps aggregate the 32 nodes' neighborhoods
// from d_xs into Xs (di applied). Phase 2: register-tiled GEMM from Xs.
__global__ __launch_bounds__(128) void k_agg_gemm1(const float* __restrict__ W1,
                                                   const float* __restrict__ b1) {
    __shared__ float Ws[64 * 128];   // 32 KB
    __shared__ float Xs[32 * 64];    // 8 KB
    int t = threadIdx.x;
    int lane = t & 31, w = t >> 5;
    int rowbase = blockIdx.x * 32;

    for (int i = t * 4; i < 64 * 128; i += 512)
        *(float4*)&Ws[i] = *(const float4*)&W1[i];

    const float2* base = (const float2*)d_xs;
    for (int nidx = w; nidx < 32; nidx += 4) {
        int node = rowbase + nidx;
        float ax = 0.f, ay = 0.f;
        if (node < NN) {
            int rs  = d_rowstart[node];
            int cnt = d_counts[node];
            float2 self = base[(size_t)node * 32 + lane];
            ax = self.x; ay = self.y;
            #pragma unroll 4
            for (int j = 0; j < cnt; j++) {
                int s = __ldg(&d_csrsrc[rs + j]);
                float2 v = base[(size_t)s * 32 + lane];
                ax += v.x; ay += v.y;
            }
            float di = d_dinv[node];
            ax *= di; ay *= di;
        }
        Xs[nidx * 64 + lane * 2]     = ax;
        Xs[nidx * 64 + lane * 2 + 1] = ay;
    }
    __syncthreads();

    int c = t & 31, rg = t >> 5;
    float4 acc[8];
    #pragma unroll
    for (int r = 0; r < 8; r++) acc[r] = make_float4(0.f, 0.f, 0.f, 0.f);
    #pragma unroll 4
    for (int k = 0; k < 64; k++) {
        float4 b = *(float4*)&Ws[k * 128 + c * 4];
        #pragma unroll
        for (int r = 0; r < 8; r++) {
            float a = Xs[(rg * 8 + r) * 64 + k];
            acc[r].x = fmaf(a, b.x, acc[r].x);
            acc[r].y = fmaf(a, b.y, acc[r].y);
            acc[r].z = fmaf(a, b.z, acc[r].z);
            acc[r].w = fmaf(a, b.w, acc[r].w);
        }
    }
    float4 bias = *(const float4*)&b1[c * 4];
    #pragma unroll
    for (int r = 0; r < 8; r++) {
        int row = rowbase + rg * 8 + r;
        if (row < NN) {
            float4 o = make_float4(fmaxf(acc[r].x + bias.x, 0.f),
                                   fmaxf(acc[r].y + bias.y, 0.f),
                                   fmaxf(acc[r].z + bias.z, 0.f),
                                   fmaxf(acc[r].w + bias.w, 0.f));
            *(float4*)&d_h1[(size_t)row * 128 + c * 4] = o;
        }
    }
}

// ---------------- GEMM2: xs2 = dinv * (h1[N,128] @ W2[128,64]) ----------------
__global__ __launch_bounds__(128) void k_gemm2(const float* __restrict__ W2) {
    __shared__ float Ws[128 * 64];
    __shared__ float Xs[32 * 128];
    int t = threadIdx.x;
    for (int i = t * 4; i < 128 * 64; i += 512)
        *(float4*)&Ws[i] = *(const float4*)&W2[i];
    int rowbase = blockIdx.x * 32;
    for (int i = t * 4; i < 32 * 128; i += 512) {
        int row = rowbase + (i >> 7);
        float4 v = (row < NN) ? *(const float4*)&d_h1[(size_t)rowbase * 128 + i]
                              : make_float4(0.f, 0.f, 0.f, 0.f);
        *(float4*)&Xs[i] = v;
    }
    __syncthreads();
    int c = t & 15, rg = t >> 4;
    float4 acc[4];
    #pragma unroll
    for (int r = 0; r < 4; r++) acc[r] = make_float4(0.f, 0.f, 0.f, 0.f);
    #pragma unroll 4
    for (int k = 0; k < 128; k++) {
        float4 b = *(float4*)&Ws[k * 64 + c * 4];
        #pragma unroll
        for (int r = 0; r < 4; r++) {
            float a = Xs[(rg * 4 + r) * 128 + k];
            acc[r].x = fmaf(a, b.x, acc[r].x);
            acc[r].y = fmaf(a, b.y, acc[r].y);
            acc[r].z = fmaf(a, b.z, acc[r].z);
            acc[r].w = fmaf(a, b.w, acc[r].w);
        }
    }
    #pragma unroll
    for (int r = 0; r < 4; r++) {
        int row = rowbase + rg * 4 + r;
        if (row < NN) {
            float di = d_dinv[row];
            float4 o = make_float4(di * acc[r].x, di * acc[r].y,
                                   di * acc[r].z, di * acc[r].w);
            *(float4*)&d_xs2[(size_t)row * 64 + c * 4] = o;
        }
    }
}

// ------- fused layer-2 aggregation + gather + MLP head, 8 rows per block -----
__global__ __launch_bounds__(256) void k_mlp(
        const int* __restrict__ ui, const int* __restrict__ ii,
        const float* __restrict__ b2,
        const float* __restrict__ fcW1, const float* __restrict__ fcb1,
        const float* __restrict__ g1,   const float* __restrict__ be1,
        const float* __restrict__ fcW2, const float* __restrict__ fcb2,
        const float* __restrict__ g2,   const float* __restrict__ be2,
        const float* __restrict__ fcW3, const float* __restrict__ fcb3,
        float* __restrict__ out) {
    __shared__ float cs[8][128];
    __shared__ float zs[8][128];
    __shared__ float rS[8][4], rQ[8][4];
    int t = threadIdx.x, lane = t & 31, w = t >> 5;   // w: 0..7
    int r0 = blockIdx.x * 8;

    // warp w aggregates user+item for row r0+w from d_xs2
    {
        int row = r0 + w;
        const float2* base = (const float2*)d_xs2;
        float2 bv = ((const float2*)b2)[lane];
        #pragma unroll
        for (int half = 0; half < 2; half++) {
            int node = (half == 0) ? (ui[row] - 1) : (ii[row] - 1 + N_USERS);
            int rs  = d_rowstart[node];
            int cnt = d_counts[node];
            float2 self = base[(size_t)node * 32 + lane];
            float ax = self.x, ay = self.y;
            #pragma unroll 4
            for (int j = 0; j < cnt; j++) {
                int s = __ldg(&d_csrsrc[rs + j]);
                float2 v = base[(size_t)s * 32 + lane];
                ax += v.x; ay += v.y;
            }
            float di = d_dinv[node];
            cs[w][half * 64 + lane * 2]     = di * ax + bv.x;
            cs[w][half * 64 + lane * 2 + 1] = di * ay + bv.y;
        }
    }
    __syncthreads();

    // fc1 [128]->[128]: group g = t>>7 handles rows g*4..g*4+3, col = t&127
    int col = t & 127;
    int g = t >> 7;
    int wg = w & 3;
    float b1v = fcb1[col];
    float accs[4] = {b1v, b1v, b1v, b1v};
    for (int k = 0; k < 128; k++) {
        float wv = fcW1[k * 128 + col];
        accs[0] = fmaf(cs[g * 4 + 0][k], wv, accs[0]);
        accs[1] = fmaf(cs[g * 4 + 1][k], wv, accs[1]);
        accs[2] = fmaf(cs[g * 4 + 2][k], wv, accs[2]);
        accs[3] = fmaf(cs[g * 4 + 3][k], wv, accs[3]);
    }
    #pragma unroll
    for (int r = 0; r < 4; r++) {
        float a = accs[r], q = accs[r] * accs[r];
        #pragma unroll
        for (int o = 16; o; o >>= 1) {
            a += __shfl_xor_sync(0xffffffffu, a, o);
            q += __shfl_xor_sync(0xffffffffu, q, o);
        }
        if (lane == 0) { rS[g * 4 + r][wg] = a; rQ[g * 4 + r][wg] = q; }
    }
    __syncthreads();
    float g1v = g1[col], be1v = be1[col];
    #pragma unroll
    for (int r = 0; r < 4; r++) {
        int row = g * 4 + r;
        float S = rS[row][0] + rS[row][1] + rS[row][2] + rS[row][3];
        float Q = rQ[row][0] + rQ[row][1] + rQ[row][2] + rQ[row][3];
        float mean = S * (1.0f / 128.0f);
        float var  = Q * (1.0f / 128.0f) - mean * mean;
        float z = fmaxf((accs[r] - mean) * rsqrtf(var + LN_EPS) * g1v + be1v, 0.f);
        zs[row][col] = z;
    }
    __syncthreads();

    // fc2 [128]->[64]: pair p = t>>6 handles rows p*2, p*2+1, col c2 = t&63
    int c2 = t & 63;
    int p = t >> 6;
    float b2v = fcb2[c2];
    float es[2] = {b2v, b2v};
    for (int k = 0; k < 128; k++) {
        float wv = fcW2[k * 64 + c2];
        es[0] = fmaf(zs[p * 2][k],     wv, es[0]);
        es[1] = fmaf(zs[p * 2 + 1][k], wv, es[1]);
    }
    #pragma unroll
    for (int i = 0; i < 2; i++) {
        float a = es[i], q = es[i] * es[i];
        #pragma unroll
        for (int o = 16; o; o >>= 1) {
            a += __shfl_xor_sync(0xffffffffu, a, o);
            q += __shfl_xor_sync(0xffffffffu, q, o);
        }
        if (lane == 0) { rS[p * 2 + i][w & 1] = a; rQ[p * 2 + i][w & 1] = q; }
    }
    __syncthreads();
    float g2v = g2[c2], be2v = be2[c2], w3 = fcW3[c2];
    float pp[2];
    #pragma unroll
    for (int i = 0; i < 2; i++) {
        int row = p * 2 + i;
        float S = rS[row][0] + rS[row][1];
        float Q = rQ[row][0] + rQ[row][1];
        float mean = S * (1.0f / 64.0f);
        float var  = Q * (1.0f / 64.0f) - mean * mean;
        float z2 = fmaxf((es[i] - mean) * rsqrtf(var + LN_EPS) * g2v + be2v, 0.f);
        pp[i] = z2 * w3;
    }
    __syncthreads();   // rS reads done before reuse
    #pragma unroll
    for (int i = 0; i < 2; i++) {
        float a = pp[i];
        #pragma unroll
        for (int o = 16; o; o >>= 1)
            a += __shfl_xor_sync(0xffffffffu, a, o);
        if (lane == 0) rS[p * 2 + i][w & 1] = a;
    }
    __syncthreads();
    if (t < 8) {
        float s = rS[t][0] + rS[t][1] + fcb3[0];
        out[r0 + t] = 1.0f / (1.0f + expf(-s));
    }
}

// ---------------- launch ----------------
extern "C" void kernel_launch(void* const* d_in, const int* in_sizes, int n_in,
                              void* d_out, int out_size) {
    const float* x    = (const float*)d_in[0];
    const int*   src  = (const int*)  d_in[1];
    const int*   dst  = (const int*)  d_in[2];
    const int*   uidx = (const int*)  d_in[3];
    const int*   iidx = (const int*)  d_in[4];
    const float* W1   = (const float*)d_in[5];
    const float* b1   = (const float*)d_in[6];
    const float* W2   = (const float*)d_in[7];
    const float* b2   = (const float*)d_in[8];
    const float* fcW1 = (const float*)d_in[9];
    const float* fcb1 = (const float*)d_in[10];
    const float* g1   = (const float*)d_in[11];
    const float* be1  = (const float*)d_in[12];
    const float* fcW2 = (const float*)d_in[13];
    const float* fcb2 = (const float*)d_in[14];
    const float* g2   = (const float*)d_in[15];
    const float* be2  = (const float*)d_in[16];
    const float* fcW3 = (const float*)d_in[17];
    const float* fcb3 = (const float*)d_in[18];
    float* out = (float*)d_out;

    // CSR build
    k_zero_counts<<<(NN + 511) / 512, 512>>>();
    k_count<<<(EE + 255) / 256, 256>>>(dst);
    k_scan1<<<NBLKS, 1024>>>();
    k_scan3<<<NBLKS, 1024>>>();
    k_fill<<<(EE + 255) / 256, 256>>>(src, dst);

    // layer 1: prescale, then fused aggregate+project
    k_prescale<<<(NN * 16 + 255) / 256, 256>>>(x);
    k_agg_gemm1<<<(NN + 31) / 32, 128>>>(W1, b1);

    // layer 2 projection (aggregation fused into MLP)
    k_gemm2<<<(NN + 31) / 32, 128>>>(W2);

    // fused agg2 + MLP head (8 pairs per block)
    k_mlp<<<BB / 8, 256>>>(uidx, iidx, b2, fcW1, fcb1, g1, be1,
                           fcW2, fcb2, g2, be2, fcW3, fcb3, out);
}

// round 6
// speedup vs baseline: 1.1606x; 1.1606x over previous
#include <cuda_runtime.h>
#include <cuda_fp16.h>
#include <math.h>

#define NN 150000
#define EE 2400000
#define BB 16384
#define N_USERS 100000
#define EMB 64
#define HID 128
#define LN_EPS 1e-5f
#define NBLKS 147   // ceil(NN/1024)

// ---------------- static scratch ----------------
__device__ __half d_xs [(size_t)NN * 64];   // fp16(dinv[n] * x[n])
__device__ float  d_ax [(size_t)NN * 64];   // A_hat @ x
__device__ float  d_h1 [(size_t)NN * 128];  // relu((A_hat x) W1 + b1)
__device__ float  d_xs2[(size_t)NN * 64];   // dinv[n] * (h1 @ W2)[n]
__device__ int    d_counts[NN];
__device__ int    d_rowstart[NN];
__device__ int    d_cursor[NN];
__device__ float  d_dinv[NN];
__device__ int    d_csrsrc[EE];
__device__ int    d_bsum[256];

// ---------------- CSR build ----------------
__global__ void k_zero_counts() {
    int i = blockIdx.x * blockDim.x + threadIdx.x;
    if (i < NN) d_counts[i] = 0;
}

__global__ void k_count(const int* __restrict__ dst) {
    int e = blockIdx.x * blockDim.x + threadIdx.x;
    if (e < EE) atomicAdd(&d_counts[dst[e]], 1);
}

__global__ void k_scan1() {
    __shared__ int s[1024];
    int t = threadIdx.x;
    int i = blockIdx.x * 1024 + t;
    int v = (i < NN) ? d_counts[i] : 0;
    s[t] = v;
    __syncthreads();
    for (int off = 1; off < 1024; off <<= 1) {
        int add = (t >= off) ? s[t - off] : 0;
        __syncthreads();
        s[t] += add;
        __syncthreads();
    }
    if (i < NN) d_rowstart[i] = s[t] - v;
    if (t == 1023) d_bsum[blockIdx.x] = s[1023];   // block total
}

// scan3: cross-block prefix computed inline by warp 0, then finalize
__global__ void k_scan3() {
    __shared__ int pref;
    int b = blockIdx.x, t = threadIdx.x;
    if (t < 32) {
        int s = 0;
        for (int j = t; j < b; j += 32) s += d_bsum[j];
        #pragma unroll
        for (int o = 16; o; o >>= 1)
            s += __shfl_xor_sync(0xffffffffu, s, o);
        if (t == 0) pref = s;
    }
    __syncthreads();
    int i = b * 1024 + t;
    if (i < NN) {
        int rs = d_rowstart[i] + pref;
        d_rowstart[i] = rs;
        d_cursor[i]   = rs;
        d_dinv[i]     = rsqrtf(1.0f + (float)d_counts[i]);
    }
}

__global__ void k_fill(const int* __restrict__ src, const int* __restrict__ dst) {
    int e = blockIdx.x * blockDim.x + threadIdx.x;
    if (e < EE) {
        int d = dst[e];
        int p = atomicAdd(&d_cursor[d], 1);
        d_csrsrc[p] = src[e];
    }
}

// ---------------- prescale: xs = fp16(dinv[n] * x[n]) ----------------
__global__ void k_prescale(const float* __restrict__ x) {
    int i = blockIdx.x * blockDim.x + threadIdx.x;     // float4 index
    if (i < NN * 16) {
        float4 v = ((const float4*)x)[i];
        float di = d_dinv[i >> 4];
        __half2 h0 = __floats2half2_rn(v.x * di, v.y * di);
        __half2 h1 = __floats2half2_rn(v.z * di, v.w * di);
        ((__half2*)d_xs)[i * 2]     = h0;
        ((__half2*)d_xs)[i * 2 + 1] = h1;
    }
}

// ---------------- aggregation layer 1 (F=64, warp per node, fp16 in) --------
__global__ void k_agg1() {
    int gw   = (blockIdx.x * blockDim.x + threadIdx.x) >> 5;
    int lane = threadIdx.x & 31;
    if (gw >= NN) return;
    int rs  = d_rowstart[gw];
    int cnt = d_counts[gw];
    const __half2* base = (const __half2*)d_xs;
    float2 self = __half22float2(base[(size_t)gw * 32 + lane]);
    float ax = self.x, ay = self.y;
    #pragma unroll 4
    for (int j = 0; j < cnt; j++) {
        int s = __ldg(&d_csrsrc[rs + j]);
        float2 v = __half22float2(base[(size_t)s * 32 + lane]);
        ax += v.x; ay += v.y;
    }
    float di = d_dinv[gw];
    ((float2*)d_ax)[(size_t)gw * 32 + lane] = make_float2(di * ax, di * ay);
}

// ---------------- GEMM1: h1 = relu(ax[N,64] @ W1[64,128] + b1) ----------------
__global__ __launch_bounds__(128) void k_gemm1(const float* __restrict__ W1,
                                               const float* __restrict__ b1) {
    __shared__ float Ws[64 * 128];
    __shared__ float Xs[32 * 64];
    int t = threadIdx.x;
    for (int i = t * 4; i < 64 * 128; i += 512)
        *(float4*)&Ws[i] = *(const float4*)&W1[i];
    int rowbase = blockIdx.x * 32;
    for (int i = t * 4; i < 32 * 64; i += 512) {
        int row = rowbase + (i >> 6);
        float4 v = (row < NN) ? *(const float4*)&d_ax[(size_t)rowbase * 64 + i]
                              : make_float4(0.f, 0.f, 0.f, 0.f);
        *(float4*)&Xs[i] = v;
    }
    __syncthreads();
    int c = t & 31, rg = t >> 5;
    float4 acc[8];
    #pragma unroll
    for (int r = 0; r < 8; r++) acc[r] = make_float4(0.f, 0.f, 0.f, 0.f);
    #pragma unroll 4
    for (int k = 0; k < 64; k++) {
        float4 b = *(float4*)&Ws[k * 128 + c * 4];
        #pragma unroll
        for (int r = 0; r < 8; r++) {
            float a = Xs[(rg * 8 + r) * 64 + k];
            acc[r].x = fmaf(a, b.x, acc[r].x);
            acc[r].y = fmaf(a, b.y, acc[r].y);
            acc[r].z = fmaf(a, b.z, acc[r].z);
            acc[r].w = fmaf(a, b.w, acc[r].w);
        }
    }
    float4 bias = *(const float4*)&b1[c * 4];
    #pragma unroll
    for (int r = 0; r < 8; r++) {
        int row = rowbase + rg * 8 + r;
        if (row < NN) {
            float4 o = make_float4(fmaxf(acc[r].x + bias.x, 0.f),
                                   fmaxf(acc[r].y + bias.y, 0.f),
                                   fmaxf(acc[r].z + bias.z, 0.f),
                                   fmaxf(acc[r].w + bias.w, 0.f));
            *(float4*)&d_h1[(size_t)row * 128 + c * 4] = o;
        }
    }
}

// ---------------- GEMM2: xs2 = dinv * (h1[N,128] @ W2[128,64]) ----------------
__global__ __launch_bounds__(128) void k_gemm2(const float* __restrict__ W2) {
    __shared__ float Ws[128 * 64];
    __shared__ float Xs[32 * 128];
    int t = threadIdx.x;
    for (int i = t * 4; i < 128 * 64; i += 512)
        *(float4*)&Ws[i] = *(const float4*)&W2[i];
    int rowbase = blockIdx.x * 32;
    for (int i = t * 4; i < 32 * 128; i += 512) {
        int row = rowbase + (i >> 7);
        float4 v = (row < NN) ? *(const float4*)&d_h1[(size_t)rowbase * 128 + i]
                              : make_float4(0.f, 0.f, 0.f, 0.f);
        *(float4*)&Xs[i] = v;
    }
    __syncthreads();
    int c = t & 15, rg = t >> 4;
    float4 acc[4];
    #pragma unroll
    for (int r = 0; r < 4; r++) acc[r] = make_float4(0.f, 0.f, 0.f, 0.f);
    #pragma unroll 4
    for (int k = 0; k < 128; k++) {
        float4 b = *(float4*)&Ws[k * 64 + c * 4];
        #pragma unroll
        for (int r = 0; r < 4; r++) {
            float a = Xs[(rg * 4 + r) * 128 + k];
            acc[r].x = fmaf(a, b.x, acc[r].x);
            acc[r].y = fmaf(a, b.y, acc[r].y);
            acc[r].z = fmaf(a, b.z, acc[r].z);
            acc[r].w = fmaf(a, b.w, acc[r].w);
        }
    }
    #pragma unroll
    for (int r = 0; r < 4; r++) {
        int row = rowbase + rg * 4 + r;
        if (row < NN) {
            float di = d_dinv[row];
            float4 o = make_float4(di * acc[r].x, di * acc[r].y,
                                   di * acc[r].z, di * acc[r].w);
            *(float4*)&d_xs2[(size_t)row * 64 + c * 4] = o;
        }
    }
}

// ------- fused layer-2 aggregation + gather + MLP head, 4 rows per block -----
__global__ __launch_bounds__(128) void k_mlp(
        const int* __restrict__ ui, const int* __restrict__ ii,
        const float* __restrict__ b2,
        const float* __restrict__ fcW1, const float* __restrict__ fcb1,
        const float* __restrict__ g1,   const float* __restrict__ be1,
        const float* __restrict__ fcW2, const float* __restrict__ fcb2,
        const float* __restrict__ g2,   const float* __restrict__ be2,
        const float* __restrict__ fcW3, const float* __restrict__ fcb3,
        float* __restrict__ out) {
    __shared__ float cs[4][128];
    __shared__ float zs[4][128];
    __shared__ float rS[4][4], rQ[4][4];
    int t = threadIdx.x, lane = t & 31, w = t >> 5;
    int r0 = blockIdx.x * 4;

    // warp w aggregates the user node then the item node for row r0+w
    {
        int row = r0 + w;
        const float2* base = (const float2*)d_xs2;
        float2 bv = ((const float2*)b2)[lane];
        #pragma unroll
        for (int half = 0; half < 2; half++) {
            int node = (half == 0) ? (ui[row] - 1) : (ii[row] - 1 + N_USERS);
            int rs  = d_rowstart[node];
            int cnt = d_counts[node];
            float2 self = base[(size_t)node * 32 + lane];
            float ax = self.x, ay = self.y;
            #pragma unroll 4
            for (int j = 0; j < cnt; j++) {
                int s = __ldg(&d_csrsrc[rs + j]);
                float2 v = base[(size_t)s * 32 + lane];
                ax += v.x; ay += v.y;
            }
            float di = d_dinv[node];
            cs[w][half * 64 + lane * 2]     = di * ax + bv.x;
            cs[w][half * 64 + lane * 2 + 1] = di * ay + bv.y;
        }
    }
    __syncthreads();

    // fc1 [128]->[128], 4 rows
    float b1v = fcb1[t];
    float accs[4] = {b1v, b1v, b1v, b1v};
    for (int k = 0; k < 128; k++) {
        float wv = fcW1[k * 128 + t];
        accs[0] = fmaf(cs[0][k], wv, accs[0]);
        accs[1] = fmaf(cs[1][k], wv, accs[1]);
        accs[2] = fmaf(cs[2][k], wv, accs[2]);
        accs[3] = fmaf(cs[3][k], wv, accs[3]);
    }
    #pragma unroll
    for (int r = 0; r < 4; r++) {
        float a = accs[r], q = accs[r] * accs[r];
        #pragma unroll
        for (int o = 16; o; o >>= 1) {
            a += __shfl_xor_sync(0xffffffffu, a, o);
            q += __shfl_xor_sync(0xffffffffu, q, o);
        }
        if (lane == 0) { rS[r][w] = a; rQ[r][w] = q; }
    }
    __syncthreads();
    float g1v = g1[t], be1v = be1[t];
    #pragma unroll
    for (int r = 0; r < 4; r++) {
        float S = rS[r][0] + rS[r][1] + rS[r][2] + rS[r][3];
        float Q = rQ[r][0] + rQ[r][1] + rQ[r][2] + rQ[r][3];
        float mean = S * (1.0f / 128.0f);
        float var  = Q * (1.0f / 128.0f) - mean * mean;
        float z = fmaxf((accs[r] - mean) * rsqrtf(var + LN_EPS) * g1v + be1v, 0.f);
        zs[r][t] = z;
    }
    __syncthreads();

    // fc2 [128]->[64]
    int c2 = t & 63;
    int rp = (t >> 6) * 2;
    float b2v = fcb2[c2];
    float es[2] = {b2v, b2v};
    for (int k = 0; k < 128; k++) {
        float wv = fcW2[k * 64 + c2];
        es[0] = fmaf(zs[rp][k],     wv, es[0]);
        es[1] = fmaf(zs[rp + 1][k], wv, es[1]);
    }
    #pragma unroll
    for (int i = 0; i < 2; i++) {
        float a = es[i], q = es[i] * es[i];
        #pragma unroll
        for (int o = 16; o; o >>= 1) {
            a += __shfl_xor_sync(0xffffffffu, a, o);
            q += __shfl_xor_sync(0xffffffffu, q, o);
        }
        if (lane == 0) { rS[rp + i][w] = a; rQ[rp + i][w] = q; }
    }
    __syncthreads();
    int wb = (t >> 6) * 2;
    float g2v = g2[c2], be2v = be2[c2], w3 = fcW3[c2];
    float p[2];
    #pragma unroll
    for (int i = 0; i < 2; i++) {
        float S = rS[rp + i][wb] + rS[rp + i][wb + 1];
        float Q = rQ[rp + i][wb] + rQ[rp + i][wb + 1];
        float mean = S * (1.0f / 64.0f);
        float var  = Q * (1.0f / 64.0f) - mean * mean;
        float z2 = fmaxf((es[i] - mean) * rsqrtf(var + LN_EPS) * g2v + be2v, 0.f);
        p[i] = z2 * w3;
    }
    __syncthreads();   // rS reads done before reuse
    #pragma unroll
    for (int i = 0; i < 2; i++) {
        float a = p[i];
        #pragma unroll
        for (int o = 16; o; o >>= 1)
            a += __shfl_xor_sync(0xffffffffu, a, o);
        if (lane == 0) rS[rp + i][w] = a;
    }
    __syncthreads();
    if (t < 4) {
        int wg = (t >> 1) * 2;
        float s = rS[t][wg] + rS[t][wg + 1] + fcb3[0];
        out[r0 + t] = 1.0f / (1.0f + expf(-s));
    }
}

// ---------------- launch ----------------
extern "C" void kernel_launch(void* const* d_in, const int* in_sizes, int n_in,
                              void* d_out, int out_size) {
    const float* x    = (const float*)d_in[0];
    const int*   src  = (const int*)  d_in[1];
    const int*   dst  = (const int*)  d_in[2];
    const int*   uidx = (const int*)  d_in[3];
    const int*   iidx = (const int*)  d_in[4];
    const float* W1   = (const float*)d_in[5];
    const float* b1   = (const float*)d_in[6];
    const float* W2   = (const float*)d_in[7];
    const float* b2   = (const float*)d_in[8];
    const float* fcW1 = (const float*)d_in[9];
    const float* fcb1 = (const float*)d_in[10];
    const float* g1   = (const float*)d_in[11];
    const float* be1  = (const float*)d_in[12];
    const float* fcW2 = (const float*)d_in[13];
    const float* fcb2 = (const float*)d_in[14];
    const float* g2   = (const float*)d_in[15];
    const float* be2  = (const float*)d_in[16];
    const float* fcW3 = (const float*)d_in[17];
    const float* fcb3 = (const float*)d_in[18];
    float* out = (float*)d_out;

    // CSR build
    k_zero_counts<<<(NN + 511) / 512, 512>>>();
    k_count<<<(EE + 255) / 256, 256>>>(dst);
    k_scan1<<<NBLKS, 1024>>>();
    k_scan3<<<NBLKS, 1024>>>();
    k_fill<<<(EE + 255) / 256, 256>>>(src, dst);

    // layer 1: prescale (fp16), aggregate (fp16 gathers), project to 128
    k_prescale<<<(NN * 16 + 255) / 256, 256>>>(x);
    k_agg1<<<(NN * 32 + 255) / 256, 256>>>();
    k_gemm1<<<(NN + 31) / 32, 128>>>(W1, b1);

    // layer 2: project to 64 (dinv prescaled); aggregation fused into k_mlp
    k_gemm2<<<(NN + 31) / 32, 128>>>(W2);

    // fused agg2 + MLP head (4 pairs per block)
    k_mlp<<<BB / 4, 128>>>(uidx, iidx, b2, fcW1, fcb1, g1, be1,
                           fcW2, fcb2, g2, be2, fcW3, fcb3, out);
}

// round 7
// speedup vs baseline: 1.2448x; 1.0725x over previous
#include <cuda_runtime.h>
#include <cuda_fp16.h>
#include <mma.h>
#include <math.h>

using namespace nvcuda;

#define NN 150000
#define EE 2400000
#define BB 16384
#define N_USERS 100000
#define EMB 64
#define HID 128
#define LN_EPS 1e-5f
#define NBLKS 147   // ceil(NN/1024)

// ---------------- static scratch ----------------
__device__ __half d_xs [(size_t)NN * 64];   // fp16(dinv[n] * x[n])
__device__ __half d_ax [(size_t)NN * 64];   // fp16(A_hat @ x)
__device__ __half d_h1 [(size_t)NN * 128];  // fp16(relu((A_hat x) W1 + b1))
__device__ __half d_xs2[(size_t)NN * 64];   // fp16(dinv[n] * (h1 @ W2)[n])
__device__ __half d_W1h[64 * 128];
__device__ __half d_W2h[128 * 64];
__device__ int    d_counts[NN];
__device__ int    d_rowstart[NN];
__device__ int    d_cursor[NN];
__device__ float  d_dinv[NN];
__device__ int    d_csrsrc[EE];
__device__ int    d_bsum[256];

// ---------------- CSR build ----------------
__global__ void k_zero_counts() {
    int i = blockIdx.x * blockDim.x + threadIdx.x;
    if (i < NN) d_counts[i] = 0;
}

__global__ void k_count(const int* __restrict__ dst) {
    int e = blockIdx.x * blockDim.x + threadIdx.x;
    if (e < EE) atomicAdd(&d_counts[dst[e]], 1);
}

__global__ void k_scan1() {
    __shared__ int s[1024];
    int t = threadIdx.x;
    int i = blockIdx.x * 1024 + t;
    int v = (i < NN) ? d_counts[i] : 0;
    s[t] = v;
    __syncthreads();
    for (int off = 1; off < 1024; off <<= 1) {
        int add = (t >= off) ? s[t - off] : 0;
        __syncthreads();
        s[t] += add;
        __syncthreads();
    }
    if (i < NN) d_rowstart[i] = s[t] - v;
    if (t == 1023) d_bsum[blockIdx.x] = s[1023];
}

__global__ void k_scan3() {
    __shared__ int pref;
    int b = blockIdx.x, t = threadIdx.x;
    if (t < 32) {
        int s = 0;
        for (int j = t; j < b; j += 32) s += d_bsum[j];
        #pragma unroll
        for (int o = 16; o; o >>= 1)
            s += __shfl_xor_sync(0xffffffffu, s, o);
        if (t == 0) pref = s;
    }
    __syncthreads();
    int i = b * 1024 + t;
    if (i < NN) {
        int rs = d_rowstart[i] + pref;
        d_rowstart[i] = rs;
        d_cursor[i]   = rs;
        d_dinv[i]     = rsqrtf(1.0f + (float)d_counts[i]);
    }
}

__global__ void k_fill(const int* __restrict__ src, const int* __restrict__ dst) {
    int e = blockIdx.x * blockDim.x + threadIdx.x;
    if (e < EE) {
        int d = dst[e];
        int p = atomicAdd(&d_cursor[d], 1);
        d_csrsrc[p] = src[e];
    }
}

// ---------------- prescale + weight conversion ----------------
__global__ void k_prescale(const float* __restrict__ x) {
    int i = blockIdx.x * blockDim.x + threadIdx.x;     // float4 index
    if (i < NN * 16) {
        float4 v = ((const float4*)x)[i];
        float di = d_dinv[i >> 4];
        ((__half2*)d_xs)[i * 2]     = __floats2half2_rn(v.x * di, v.y * di);
        ((__half2*)d_xs)[i * 2 + 1] = __floats2half2_rn(v.z * di, v.w * di);
    }
}

__global__ void k_cvtw(const float* __restrict__ W1, const float* __restrict__ W2) {
    int i = blockIdx.x * blockDim.x + threadIdx.x;
    if (i < 8192)       d_W1h[i]        = __float2half(W1[i]);
    else if (i < 16384) d_W2h[i - 8192] = __float2half(W2[i - 8192]);
}

// ---------------- aggregation layer 1 (F=64, warp per node) ----------------
__global__ void k_agg1() {
    int gw   = (blockIdx.x * blockDim.x + threadIdx.x) >> 5;
    int lane = threadIdx.x & 31;
    if (gw >= NN) return;
    int rs  = d_rowstart[gw];
    int cnt = d_counts[gw];
    const __half2* base = (const __half2*)d_xs;
    float2 self = __half22float2(base[(size_t)gw * 32 + lane]);
    float ax = self.x, ay = self.y;
    #pragma unroll 4
    for (int j = 0; j < cnt; j++) {
        int s = __ldg(&d_csrsrc[rs + j]);
        float2 v = __half22float2(base[(size_t)s * 32 + lane]);
        ax += v.x; ay += v.y;
    }
    float di = d_dinv[gw];
    ((__half2*)d_ax)[(size_t)gw * 32 + lane] = __floats2half2_rn(di * ax, di * ay);
}

// ------- GEMM1 (wmma): h1 = fp16(relu(ax[N,64] @ W1[64,128] + b1)) ---------
// 64-row block tile, 256 threads = 8 warps (4 row-groups x 2 col-groups).
__global__ __launch_bounds__(256) void k_gemm1(const float* __restrict__ b1) {
    __shared__ __half As[64 * 64];        // 8 KB
    __shared__ __half Bs[64 * 128];       // 16 KB
    __shared__ float  St[8][16 * 20];     // 10 KB staging, ld=20
    int t = threadIdx.x;
    int rowbase = blockIdx.x * 64;

    for (int i = t; i < 64 * 32; i += 256) {       // half2 index, row = i>>5
        int row = rowbase + (i >> 5);
        ((__half2*)As)[i] = (row < NN) ? ((const __half2*)d_ax)[(size_t)rowbase * 32 + i]
                                       : __floats2half2_rn(0.f, 0.f);
    }
    for (int i = t; i < 4096; i += 256)
        ((__half2*)Bs)[i] = ((const __half2*)d_W1h)[i];
    __syncthreads();

    int w  = t >> 5, lane = t & 31;
    int wr = w >> 1;           // row group 0..3
    int wc = w & 1;            // col group 0..1 (64 cols)
    wmma::fragment<wmma::accumulator, 16, 16, 16, float> cf[4];
    #pragma unroll
    for (int j = 0; j < 4; j++) wmma::fill_fragment(cf[j], 0.0f);
    #pragma unroll
    for (int k = 0; k < 4; k++) {
        wmma::fragment<wmma::matrix_a, 16, 16, 16, __half, wmma::row_major> af;
        wmma::load_matrix_sync(af, As + (wr * 16) * 64 + k * 16, 64);
        #pragma unroll
        for (int j = 0; j < 4; j++) {
            wmma::fragment<wmma::matrix_b, 16, 16, 16, __half, wmma::row_major> bf;
            wmma::load_matrix_sync(bf, Bs + (k * 16) * 128 + wc * 64 + j * 16, 128);
            wmma::mma_sync(cf[j], af, bf, cf[j]);
        }
    }
    // epilogue per fragment: stage -> bias+relu -> fp16
    #pragma unroll
    for (int j = 0; j < 4; j++) {
        wmma::store_matrix_sync(St[w], cf[j], 20, wmma::mem_row_major);
        __syncwarp();
        int colbase = wc * 64 + j * 16;
        for (int i = lane; i < 128; i += 32) {     // half2 elems: 16 rows x 8
            int lr = i >> 3, c2 = (i & 7) * 2;
            int row = rowbase + wr * 16 + lr;
            if (row < NN) {
                float v0 = fmaxf(St[w][lr * 20 + c2]     + b1[colbase + c2], 0.f);
                float v1 = fmaxf(St[w][lr * 20 + c2 + 1] + b1[colbase + c2 + 1], 0.f);
                ((__half2*)d_h1)[(size_t)row * 64 + (colbase >> 1) + (i & 7)] =
                    __floats2half2_rn(v0, v1);
            }
        }
        __syncwarp();
    }
}

// ------- GEMM2 (wmma): xs2 = fp16(dinv * (h1[N,128] @ W2[128,64])) ---------
// 64-row block tile, 256 threads = 8 warps (4 row-groups x 2 col-groups of 32).
__global__ __launch_bounds__(256) void k_gemm2() {
    __shared__ __half As[64 * 128];       // 16 KB
    __shared__ __half Bs[128 * 64];       // 16 KB
    __shared__ float  St[8][16 * 20];     // 10 KB
    int t = threadIdx.x;
    int rowbase = blockIdx.x * 64;

    for (int i = t; i < 64 * 64; i += 256) {       // half2 index, row = i>>6
        int row = rowbase + (i >> 6);
        ((__half2*)As)[i] = (row < NN) ? ((const __half2*)d_h1)[(size_t)rowbase * 64 + i]
                                       : __floats2half2_rn(0.f, 0.f);
    }
    for (int i = t; i < 4096; i += 256)
        ((__half2*)Bs)[i] = ((const __half2*)d_W2h)[i];
    __syncthreads();

    int w  = t >> 5, lane = t & 31;
    int wr = w >> 1;           // row group 0..3
    int wc = w & 1;            // col group 0..1 (32 cols)
    wmma::fragment<wmma::accumulator, 16, 16, 16, float> cf[2];
    #pragma unroll
    for (int j = 0; j < 2; j++) wmma::fill_fragment(cf[j], 0.0f);
    #pragma unroll
    for (int k = 0; k < 8; k++) {
        wmma::fragment<wmma::matrix_a, 16, 16, 16, __half, wmma::row_major> af;
        wmma::load_matrix_sync(af, As + (wr * 16) * 128 + k * 16, 128);
        #pragma unroll
        for (int j = 0; j < 2; j++) {
            wmma::fragment<wmma::matrix_b, 16, 16, 16, __half, wmma::row_major> bf;
            wmma::load_matrix_sync(bf, Bs + (k * 16) * 64 + wc * 32 + j * 16, 64);
            wmma::mma_sync(cf[j], af, bf, cf[j]);
        }
    }
    #pragma unroll
    for (int j = 0; j < 2; j++) {
        wmma::store_matrix_sync(St[w], cf[j], 20, wmma::mem_row_major);
        __syncwarp();
        int colbase = wc * 32 + j * 16;
        for (int i = lane; i < 128; i += 32) {     // half2 elems: 16 rows x 8
            int lr = i >> 3, c2 = (i & 7) * 2;
            int row = rowbase + wr * 16 + lr;
            if (row < NN) {
                float di = d_dinv[row];
                float v0 = di * St[w][lr * 20 + c2];
                float v1 = di * St[w][lr * 20 + c2 + 1];
                ((__half2*)d_xs2)[(size_t)row * 32 + (colbase >> 1) + (i & 7)] =
                    __floats2half2_rn(v0, v1);
            }
        }
        __syncwarp();
    }
}

// ------- fused layer-2 aggregation + gather + MLP head, 4 rows per block -----
__global__ __launch_bounds__(128) void k_mlp(
        const int* __restrict__ ui, const int* __restrict__ ii,
        const float* __restrict__ b2,
        const float* __restrict__ fcW1, const float* __restrict__ fcb1,
        const float* __restrict__ g1,   const float* __restrict__ be1,
        const float* __restrict__ fcW2, const float* __restrict__ fcb2,
        const float* __restrict__ g2,   const float* __restrict__ be2,
        const float* __restrict__ fcW3, const float* __restrict__ fcb3,
        float* __restrict__ out) {
    __shared__ float cs[4][128];
    __shared__ float zs[4][128];
    __shared__ float rS[4][4], rQ[4][4];
    int t = threadIdx.x, lane = t & 31, w = t >> 5;
    int r0 = blockIdx.x * 4;

    // warp w aggregates the user node then the item node for row r0+w
    {
        int row = r0 + w;
        const __half2* base = (const __half2*)d_xs2;
        float2 bv = ((const float2*)b2)[lane];
        #pragma unroll
        for (int half = 0; half < 2; half++) {
            int node = (half == 0) ? (ui[row] - 1) : (ii[row] - 1 + N_USERS);
            int rs  = d_rowstart[node];
            int cnt = d_counts[node];
            float2 self = __half22float2(base[(size_t)node * 32 + lane]);
            float ax = self.x, ay = self.y;
            #pragma unroll 4
            for (int j = 0; j < cnt; j++) {
                int s = __ldg(&d_csrsrc[rs + j]);
                float2 v = __half22float2(base[(size_t)s * 32 + lane]);
                ax += v.x; ay += v.y;
            }
            float di = d_dinv[node];
            cs[w][half * 64 + lane * 2]     = di * ax + bv.x;
            cs[w][half * 64 + lane * 2 + 1] = di * ay + bv.y;
        }
    }
    __syncthreads();

    // fc1 [128]->[128], 4 rows
    float b1v = fcb1[t];
    float accs[4] = {b1v, b1v, b1v, b1v};
    for (int k = 0; k < 128; k++) {
        float wv = fcW1[k * 128 + t];
        accs[0] = fmaf(cs[0][k], wv, accs[0]);
        accs[1] = fmaf(cs[1][k], wv, accs[1]);
        accs[2] = fmaf(cs[2][k], wv, accs[2]);
        accs[3] = fmaf(cs[3][k], wv, accs[3]);
    }
    #pragma unroll
    for (int r = 0; r < 4; r++) {
        float a = accs[r], q = accs[r] * accs[r];
        #pragma unroll
        for (int o = 16; o; o >>= 1) {
            a += __shfl_xor_sync(0xffffffffu, a, o);
            q += __shfl_xor_sync(0xffffffffu, q, o);
        }
        if (lane == 0) { rS[r][w] = a; rQ[r][w] = q; }
    }
    __syncthreads();
    float g1v = g1[t], be1v = be1[t];
    #pragma unroll
    for (int r = 0; r < 4; r++) {
        float S = rS[r][0] + rS[r][1] + rS[r][2] + rS[r][3];
        float Q = rQ[r][0] + rQ[r][1] + rQ[r][2] + rQ[r][3];
        float mean = S * (1.0f / 128.0f);
        float var  = Q * (1.0f / 128.0f) - mean * mean;
        float z = fmaxf((accs[r] - mean) * rsqrtf(var + LN_EPS) * g1v + be1v, 0.f);
        zs[r][t] = z;
    }
    __syncthreads();

    // fc2 [128]->[64]
    int c2 = t & 63;
    int rp = (t >> 6) * 2;
    float b2v = fcb2[c2];
    float es[2] = {b2v, b2v};
    for (int k = 0; k < 128; k++) {
        float wv = fcW2[k * 64 + c2];
        es[0] = fmaf(zs[rp][k],     wv, es[0]);
        es[1] = fmaf(zs[rp + 1][k], wv, es[1]);
    }
    #pragma unroll
    for (int i = 0; i < 2; i++) {
        float a = es[i], q = es[i] * es[i];
        #pragma unroll
        for (int o = 16; o; o >>= 1) {
            a += __shfl_xor_sync(0xffffffffu, a, o);
            q += __shfl_xor_sync(0xffffffffu, q, o);
        }
        if (lane == 0) { rS[rp + i][w] = a; rQ[rp + i][w] = q; }
    }
    __syncthreads();
    int wb = (t >> 6) * 2;
    float g2v = g2[c2], be2v = be2[c2], w3 = fcW3[c2];
    float p[2];
    #pragma unroll
    for (int i = 0; i < 2; i++) {
        float S = rS[rp + i][wb] + rS[rp + i][wb + 1];
        float Q = rQ[rp + i][wb] + rQ[rp + i][wb + 1];
        float mean = S * (1.0f / 64.0f);
        float var  = Q * (1.0f / 64.0f) - mean * mean;
        float z2 = fmaxf((es[i] - mean) * rsqrtf(var + LN_EPS) * g2v + be2v, 0.f);
        p[i] = z2 * w3;
    }
    __syncthreads();   // rS reads done before reuse
    #pragma unroll
    for (int i = 0; i < 2; i++) {
        float a = p[i];
        #pragma unroll
        for (int o = 16; o; o >>= 1)
            a += __shfl_xor_sync(0xffffffffu, a, o);
        if (lane == 0) rS[rp + i][w] = a;
    }
    __syncthreads();
    if (t < 4) {
        int wg = (t >> 1) * 2;
        float s = rS[t][wg] + rS[t][wg + 1] + fcb3[0];
        out[r0 + t] = 1.0f / (1.0f + expf(-s));
    }
}

// ---------------- launch ----------------
extern "C" void kernel_launch(void* const* d_in, const int* in_sizes, int n_in,
                              void* d_out, int out_size) {
    const float* x    = (const float*)d_in[0];
    const int*   src  = (const int*)  d_in[1];
    const int*   dst  = (const int*)  d_in[2];
    const int*   uidx = (const int*)  d_in[3];
    const int*   iidx = (const int*)  d_in[4];
    const float* W1   = (const float*)d_in[5];
    const float* b1   = (const float*)d_in[6];
    const float* W2   = (const float*)d_in[7];
    const float* b2   = (const float*)d_in[8];
    const float* fcW1 = (const float*)d_in[9];
    const float* fcb1 = (const float*)d_in[10];
    const float* g1   = (const float*)d_in[11];
    const float* be1  = (const float*)d_in[12];
    const float* fcW2 = (const float*)d_in[13];
    const float* fcb2 = (const float*)d_in[14];
    const float* g2   = (const float*)d_in[15];
    const float* be2  = (const float*)d_in[16];
    const float* fcW3 = (const float*)d_in[17];
    const float* fcb3 = (const float*)d_in[18];
    float* out = (float*)d_out;

    // CSR build
    k_zero_counts<<<(NN + 511) / 512, 512>>>();
    k_count<<<(EE + 255) / 256, 256>>>(dst);
    k_scan1<<<NBLKS, 1024>>>();
    k_scan3<<<NBLKS, 1024>>>();
    k_fill<<<(EE + 255) / 256, 256>>>(src, dst);

    // conversions
    k_cvtw<<<(16384 + 255) / 256, 256>>>(W1, W2);
    k_prescale<<<(NN * 16 + 255) / 256, 256>>>(x);

    // layer 1: aggregate (fp16 gathers), tensor-core project to 128
    k_agg1<<<(NN * 32 + 255) / 256, 256>>>();
    k_gemm1<<<(NN + 63) / 64, 256>>>(b1);

    // layer 2: tensor-core project to 64 (dinv prescaled); agg fused into k_mlp
    k_gemm2<<<(NN + 63) / 64, 256>>>();

    // fused agg2 + MLP head (4 pairs per block)
    k_mlp<<<BB / 4, 128>>>(uidx, iidx, b2, fcW1, fcb1, g1, be1,
                           fcW2, fcb2, g2, be2, fcW3, fcb3, out);
}

// round 8
// speedup vs baseline: 1.2462x; 1.0012x over previous
#include <cuda_runtime.h>
#include <cuda_fp16.h>
#include <mma.h>
#include <math.h>

using namespace nvcuda;

#define NN 150000
#define EE 2400000
#define BB 16384
#define N_USERS 100000
#define EMB 64
#define HID 128
#define LN_EPS 1e-5f
#define NBLKS 147   // ceil(NN/1024)

// ---------------- static scratch ----------------
__device__ __half d_xs [(size_t)NN * 64];   // fp16(dinv[n] * x[n])
__device__ __half d_ax [(size_t)NN * 64];   // fp16(A_hat @ x)
__device__ __half d_h1 [(size_t)NN * 128];  // fp16(relu((A_hat x) W1 + b1))
__device__ __half d_xs2[(size_t)NN * 64];   // fp16(dinv[n] * (h1 @ W2)[n])
__device__ __half d_W1h[64 * 128];
__device__ __half d_W2h[128 * 64];
__device__ __half d_fcW1h[128 * 128];
__device__ __half d_fcW2h[128 * 64];
__device__ int    d_counts[NN];
__device__ int    d_rowstart[NN];
__device__ int    d_cursor[NN];
__device__ float  d_dinv[NN];
__device__ int    d_csrsrc[EE];
__device__ int    d_bsum[256];

// ------------- init: zero counts + convert all weights to fp16 -------------
__global__ void k_init(const float* __restrict__ W1, const float* __restrict__ W2,
                       const float* __restrict__ fcW1, const float* __restrict__ fcW2) {
    int i = blockIdx.x * blockDim.x + threadIdx.x;
    if (i < NN) d_counts[i] = 0;
    if (i < 8192)       d_W1h[i]        = __float2half(W1[i]);
    else if (i < 16384) d_W2h[i - 8192] = __float2half(W2[i - 8192]);
    if (i < 16384)      d_fcW1h[i]          = __float2half(fcW1[i]);
    else if (i < 24576) d_fcW2h[i - 16384]  = __float2half(fcW2[i - 16384]);
}

__global__ void k_count(const int* __restrict__ dst) {
    int e = blockIdx.x * blockDim.x + threadIdx.x;
    if (e < EE) atomicAdd(&d_counts[dst[e]], 1);
}

__global__ void k_scan1() {
    __shared__ int s[1024];
    int t = threadIdx.x;
    int i = blockIdx.x * 1024 + t;
    int v = (i < NN) ? d_counts[i] : 0;
    s[t] = v;
    __syncthreads();
    for (int off = 1; off < 1024; off <<= 1) {
        int add = (t >= off) ? s[t - off] : 0;
        __syncthreads();
        s[t] += add;
        __syncthreads();
    }
    if (i < NN) d_rowstart[i] = s[t] - v;
    if (t == 1023) d_bsum[blockIdx.x] = s[1023];
}

// scan3: cross-block prefix + finalize rowstart/cursor/dinv + FUSED prescale
__global__ void k_scan3(const float* __restrict__ x) {
    __shared__ int pref;
    __shared__ float sdinv[1024];
    int b = blockIdx.x, t = threadIdx.x;
    if (t < 32) {
        int s = 0;
        for (int j = t; j < b; j += 32) s += d_bsum[j];
        #pragma unroll
        for (int o = 16; o; o >>= 1)
            s += __shfl_xor_sync(0xffffffffu, s, o);
        if (t == 0) pref = s;
    }
    __syncthreads();
    int i = b * 1024 + t;
    float di = 0.f;
    if (i < NN) {
        int rs = d_rowstart[i] + pref;
        d_rowstart[i] = rs;
        d_cursor[i]   = rs;
        di = rsqrtf(1.0f + (float)d_counts[i]);
        d_dinv[i] = di;
    }
    sdinv[t] = di;
    __syncthreads();
    // prescale this block's 1024 nodes: d_xs[n] = fp16(dinv[n] * x[n])
    int nb = b * 1024;
    for (int e = t; e < 1024 * 32; e += 1024) {      // half2/float2 elements
        int node = nb + (e >> 5);
        if (node < NN) {
            float2 v = ((const float2*)x)[(size_t)node * 32 + (e & 31)];
            float d = sdinv[e >> 5];
            ((__half2*)d_xs)[(size_t)node * 32 + (e & 31)] =
                __floats2half2_rn(v.x * d, v.y * d);
        }
    }
}

__global__ void k_fill(const int* __restrict__ src, const int* __restrict__ dst) {
    int e = blockIdx.x * blockDim.x + threadIdx.x;
    if (e < EE) {
        int d = dst[e];
        int p = atomicAdd(&d_cursor[d], 1);
        d_csrsrc[p] = src[e];
    }
}

// ---------------- aggregation layer 1 (F=64, warp per node) ----------------
__global__ void k_agg1() {
    int gw   = (blockIdx.x * blockDim.x + threadIdx.x) >> 5;
    int lane = threadIdx.x & 31;
    if (gw >= NN) return;
    int rs  = d_rowstart[gw];
    int cnt = d_counts[gw];
    const __half2* base = (const __half2*)d_xs;
    float2 self = __half22float2(base[(size_t)gw * 32 + lane]);
    float ax = self.x, ay = self.y;
    #pragma unroll 4
    for (int j = 0; j < cnt; j++) {
        int s = __ldg(&d_csrsrc[rs + j]);
        float2 v = __half22float2(base[(size_t)s * 32 + lane]);
        ax += v.x; ay += v.y;
    }
    float di = d_dinv[gw];
    ((__half2*)d_ax)[(size_t)gw * 32 + lane] = __floats2half2_rn(di * ax, di * ay);
}

// ------- GEMM1 (wmma): h1 = fp16(relu(ax[N,64] @ W1[64,128] + b1)) ---------
__global__ __launch_bounds__(256) void k_gemm1(const float* __restrict__ b1) {
    __shared__ __half As[64 * 64];
    __shared__ __half Bs[64 * 128];
    __shared__ float  St[8][16 * 20];
    int t = threadIdx.x;
    int rowbase = blockIdx.x * 64;

    for (int i = t; i < 64 * 32; i += 256) {
        int row = rowbase + (i >> 5);
        ((__half2*)As)[i] = (row < NN) ? ((const __half2*)d_ax)[(size_t)rowbase * 32 + i]
                                       : __floats2half2_rn(0.f, 0.f);
    }
    for (int i = t; i < 4096; i += 256)
        ((__half2*)Bs)[i] = ((const __half2*)d_W1h)[i];
    __syncthreads();

    int w  = t >> 5, lane = t & 31;
    int wr = w >> 1;
    int wc = w & 1;
    wmma::fragment<wmma::accumulator, 16, 16, 16, float> cf[4];
    #pragma unroll
    for (int j = 0; j < 4; j++) wmma::fill_fragment(cf[j], 0.0f);
    #pragma unroll
    for (int k = 0; k < 4; k++) {
        wmma::fragment<wmma::matrix_a, 16, 16, 16, __half, wmma::row_major> af;
        wmma::load_matrix_sync(af, As + (wr * 16) * 64 + k * 16, 64);
        #pragma unroll
        for (int j = 0; j < 4; j++) {
            wmma::fragment<wmma::matrix_b, 16, 16, 16, __half, wmma::row_major> bf;
            wmma::load_matrix_sync(bf, Bs + (k * 16) * 128 + wc * 64 + j * 16, 128);
            wmma::mma_sync(cf[j], af, bf, cf[j]);
        }
    }
    #pragma unroll
    for (int j = 0; j < 4; j++) {
        wmma::store_matrix_sync(St[w], cf[j], 20, wmma::mem_row_major);
        __syncwarp();
        int colbase = wc * 64 + j * 16;
        for (int i = lane; i < 128; i += 32) {
            int lr = i >> 3, c2 = (i & 7) * 2;
            int row = rowbase + wr * 16 + lr;
            if (row < NN) {
                float v0 = fmaxf(St[w][lr * 20 + c2]     + b1[colbase + c2], 0.f);
                float v1 = fmaxf(St[w][lr * 20 + c2 + 1] + b1[colbase + c2 + 1], 0.f);
                ((__half2*)d_h1)[(size_t)row * 64 + (colbase >> 1) + (i & 7)] =
                    __floats2half2_rn(v0, v1);
            }
        }
        __syncwarp();
    }
}

// ------- GEMM2 (wmma): xs2 = fp16(dinv * (h1[N,128] @ W2[128,64])) ---------
__global__ __launch_bounds__(256) void k_gemm2() {
    __shared__ __half As[64 * 128];
    __shared__ __half Bs[128 * 64];
    __shared__ float  St[8][16 * 20];
    int t = threadIdx.x;
    int rowbase = blockIdx.x * 64;

    for (int i = t; i < 64 * 64; i += 256) {
        int row = rowbase + (i >> 6);
        ((__half2*)As)[i] = (row < NN) ? ((const __half2*)d_h1)[(size_t)rowbase * 64 + i]
                                       : __floats2half2_rn(0.f, 0.f);
    }
    for (int i = t; i < 4096; i += 256)
        ((__half2*)Bs)[i] = ((const __half2*)d_W2h)[i];
    __syncthreads();

    int w  = t >> 5, lane = t & 31;
    int wr = w >> 1;
    int wc = w & 1;
    wmma::fragment<wmma::accumulator, 16, 16, 16, float> cf[2];
    #pragma unroll
    for (int j = 0; j < 2; j++) wmma::fill_fragment(cf[j], 0.0f);
    #pragma unroll
    for (int k = 0; k < 8; k++) {
        wmma::fragment<wmma::matrix_a, 16, 16, 16, __half, wmma::row_major> af;
        wmma::load_matrix_sync(af, As + (wr * 16) * 128 + k * 16, 128);
        #pragma unroll
        for (int j = 0; j < 2; j++) {
            wmma::fragment<wmma::matrix_b, 16, 16, 16, __half, wmma::row_major> bf;
            wmma::load_matrix_sync(bf, Bs + (k * 16) * 64 + wc * 32 + j * 16, 64);
            wmma::mma_sync(cf[j], af, bf, cf[j]);
        }
    }
    #pragma unroll
    for (int j = 0; j < 2; j++) {
        wmma::store_matrix_sync(St[w], cf[j], 20, wmma::mem_row_major);
        __syncwarp();
        int colbase = wc * 32 + j * 16;
        for (int i = lane; i < 128; i += 32) {
            int lr = i >> 3, c2 = (i & 7) * 2;
            int row = rowbase + wr * 16 + lr;
            if (row < NN) {
                float di = d_dinv[row];
                float v0 = di * St[w][lr * 20 + c2];
                float v1 = di * St[w][lr * 20 + c2 + 1];
                ((__half2*)d_xs2)[(size_t)row * 32 + (colbase >> 1) + (i & 7)] =
                    __floats2half2_rn(v0, v1);
            }
        }
        __syncwarp();
    }
}

// ------ fused layer-2 agg + MLP head: 8 rows/block, fp16 weights ------------
__global__ __launch_bounds__(256) void k_mlp(
        const int* __restrict__ ui, const int* __restrict__ ii,
        const float* __restrict__ b2,
        const float* __restrict__ fcb1,
        const float* __restrict__ g1,   const float* __restrict__ be1,
        const float* __restrict__ fcb2,
        const float* __restrict__ g2,   const float* __restrict__ be2,
        const float* __restrict__ fcW3, const float* __restrict__ fcb3,
        float* __restrict__ out) {
    __shared__ float cs[8][128];
    __shared__ float zs[8][128];
    __shared__ float rS[8][2], rQ[8][2];
    int t = threadIdx.x, lane = t & 31, w = t >> 5;   // w: 0..7
    int r0 = blockIdx.x * 8;

    // warp w aggregates user+item for row r0+w from d_xs2 (layer-2 agg)
    {
        int row = r0 + w;
        const __half2* base = (const __half2*)d_xs2;
        float2 bv = ((const float2*)b2)[lane];
        #pragma unroll
        for (int half = 0; half < 2; half++) {
            int node = (half == 0) ? (ui[row] - 1) : (ii[row] - 1 + N_USERS);
            int rs  = d_rowstart[node];
            int cnt = d_counts[node];
            float2 self = __half22float2(base[(size_t)node * 32 + lane]);
            float ax = self.x, ay = self.y;
            #pragma unroll 4
            for (int j = 0; j < cnt; j++) {
                int s = __ldg(&d_csrsrc[rs + j]);
                float2 v = __half22float2(base[(size_t)s * 32 + lane]);
                ax += v.x; ay += v.y;
            }
            float di = d_dinv[node];
            cs[w][half * 64 + lane * 2]     = di * ax + bv.x;
            cs[w][half * 64 + lane * 2 + 1] = di * ay + bv.y;
        }
    }
    __syncthreads();

    // ---- fc1 [128]->[128]: thread = colpair c2 for group g (rows 2g,2g+1) ----
    int c2 = t & 63;            // column pair: cols 2c2, 2c2+1
    int g  = t >> 6;            // 0..3 -> rows 2g, 2g+1 ; warps 2g,2g+1
    int wg = w & 1;
    const __half2* W1h = (const __half2*)d_fcW1h;
    float2 b1v = ((const float2*)fcb1)[c2];
    float a0x = b1v.x, a0y = b1v.y, a1x = b1v.x, a1y = b1v.y;
    #pragma unroll 8
    for (int k = 0; k < 128; k++) {
        float2 wv = __half22float2(W1h[k * 64 + c2]);
        float v0 = cs[2 * g][k], v1 = cs[2 * g + 1][k];
        a0x = fmaf(v0, wv.x, a0x); a0y = fmaf(v0, wv.y, a0y);
        a1x = fmaf(v1, wv.x, a1x); a1y = fmaf(v1, wv.y, a1y);
    }
    // LN: row 2g over group's 64 threads (warps 2g,2g+1)
    float s0 = a0x + a0y, q0 = a0x * a0x + a0y * a0y;
    float s1 = a1x + a1y, q1 = a1x * a1x + a1y * a1y;
    #pragma unroll
    for (int o = 16; o; o >>= 1) {
        s0 += __shfl_xor_sync(0xffffffffu, s0, o);
        q0 += __shfl_xor_sync(0xffffffffu, q0, o);
        s1 += __shfl_xor_sync(0xffffffffu, s1, o);
        q1 += __shfl_xor_sync(0xffffffffu, q1, o);
    }
    if (lane == 0) {
        rS[2 * g][wg] = s0; rQ[2 * g][wg] = q0;
        rS[2 * g + 1][wg] = s1; rQ[2 * g + 1][wg] = q1;
    }
    __syncthreads();
    {
        float2 g1v = ((const float2*)g1)[c2];
        float2 be1v = ((const float2*)be1)[c2];
        float S0 = rS[2 * g][0] + rS[2 * g][1];
        float Q0 = rQ[2 * g][0] + rQ[2 * g][1];
        float S1 = rS[2 * g + 1][0] + rS[2 * g + 1][1];
        float Q1 = rQ[2 * g + 1][0] + rQ[2 * g + 1][1];
        float m0 = S0 * (1.f / 128.f), v0 = Q0 * (1.f / 128.f) - m0 * m0;
        float m1 = S1 * (1.f / 128.f), v1 = Q1 * (1.f / 128.f) - m1 * m1;
        float r0s = rsqrtf(v0 + LN_EPS), r1s = rsqrtf(v1 + LN_EPS);
        float z0x = fmaxf((a0x - m0) * r0s * g1v.x + be1v.x, 0.f);
        float z0y = fmaxf((a0y - m0) * r0s * g1v.y + be1v.y, 0.f);
        float z1x = fmaxf((a1x - m1) * r1s * g1v.x + be1v.x, 0.f);
        float z1y = fmaxf((a1y - m1) * r1s * g1v.y + be1v.y, 0.f);
        ((float2*)zs[2 * g])[c2]     = make_float2(z0x, z0y);
        ((float2*)zs[2 * g + 1])[c2] = make_float2(z1x, z1y);
    }
    __syncthreads();

    // ---- fc2 [128]->[64]: warp w = row, lane = colpair; LN via shuffles ----
    {
        const __half2* W2h = (const __half2*)d_fcW2h;
        float2 b2v = ((const float2*)fcb2)[lane];
        float ax = b2v.x, ay = b2v.y;
        #pragma unroll 8
        for (int k = 0; k < 128; k++) {
            float2 wv = __half22float2(W2h[k * 32 + lane]);
            float v = zs[w][k];
            ax = fmaf(v, wv.x, ax); ay = fmaf(v, wv.y, ay);
        }
        float a = ax + ay, q = ax * ax + ay * ay;
        #pragma unroll
        for (int o = 16; o; o >>= 1) {
            a += __shfl_xor_sync(0xffffffffu, a, o);
            q += __shfl_xor_sync(0xffffffffu, q, o);
        }
        float mean = a * (1.f / 64.f);
        float var  = q * (1.f / 64.f) - mean * mean;
        float rstd = rsqrtf(var + LN_EPS);
        float2 g2v = ((const float2*)g2)[lane];
        float2 be2v = ((const float2*)be2)[lane];
        float2 w3v = ((const float2*)fcW3)[lane];
        float z0 = fmaxf((ax - mean) * rstd * g2v.x + be2v.x, 0.f);
        float z1 = fmaxf((ay - mean) * rstd * g2v.y + be2v.y, 0.f);
        float p = z0 * w3v.x + z1 * w3v.y;
        #pragma unroll
        for (int o = 16; o; o >>= 1)
            p += __shfl_xor_sync(0xffffffffu, p, o);
        if (lane == 0)
            out[r0 + w] = 1.0f / (1.0f + expf(-(p + fcb3[0])));
    }
}

// ---------------- launch ----------------
extern "C" void kernel_launch(void* const* d_in, const int* in_sizes, int n_in,
                              void* d_out, int out_size) {
    const float* x    = (const float*)d_in[0];
    const int*   src  = (const int*)  d_in[1];
    const int*   dst  = (const int*)  d_in[2];
    const int*   uidx = (const int*)  d_in[3];
    const int*   iidx = (const int*)  d_in[4];
    const float* W1   = (const float*)d_in[5];
    const float* b1   = (const float*)d_in[6];
    const float* W2   = (const float*)d_in[7];
    const float* b2   = (const float*)d_in[8];
    const float* fcW1 = (const float*)d_in[9];
    const float* fcb1 = (const float*)d_in[10];
    const float* g1   = (const float*)d_in[11];
    const float* be1  = (const float*)d_in[12];
    const float* fcW2 = (const float*)d_in[13];
    const float* fcb2 = (const float*)d_in[14];
    const float* g2   = (const float*)d_in[15];
    const float* be2  = (const float*)d_in[16];
    const float* fcW3 = (const float*)d_in[17];
    const float* fcb3 = (const float*)d_in[18];
    float* out = (float*)d_out;

    // CSR build (+ weight conversion, + fused prescale in scan3)
    k_init<<<(NN + 255) / 256, 256>>>(W1, W2, fcW1, fcW2);
    k_count<<<(EE + 255) / 256, 256>>>(dst);
    k_scan1<<<NBLKS, 1024>>>();
    k_scan3<<<NBLKS, 1024>>>(x);
    k_fill<<<(EE + 255) / 256, 256>>>(src, dst);

    // layer 1: aggregate (fp16 gathers), tensor-core project to 128
    k_agg1<<<(NN * 32 + 255) / 256, 256>>>();
    k_gemm1<<<(NN + 63) / 64, 256>>>(b1);

    // layer 2: tensor-core project to 64 (dinv prescaled); agg fused into k_mlp
    k_gemm2<<<(NN + 63) / 64, 256>>>();

    // fused agg2 + MLP head (8 pairs per block, fp16 weights)
    k_mlp<<<BB / 8, 256>>>(uidx, iidx, b2, fcb1, g1, be1,
                           fcb2, g2, be2, fcW3, fcb3, out);
}

// round 9
// speedup vs baseline: 1.3710x; 1.1001x over previous
#include <cuda_runtime.h>
#include <cuda_fp16.h>
#include <mma.h>
#include <math.h>

using namespace nvcuda;

#define NN 150000
#define EE 2400000
#define BB 16384
#define N_USERS 100000
#define EMB 64
#define HID 128
#define LN_EPS 1e-5f
#define NBLKS 147   // ceil(NN/1024)

// ---------------- static scratch ----------------
__device__ __half d_xs [(size_t)NN * 64];   // fp16(dinv[n] * x[n])
__device__ __half d_ax [(size_t)NN * 64];   // fp16(A_hat @ x)
__device__ __half d_xs2[(size_t)NN * 64];   // fp16(dinv[n] * (relu((A x)W1+b1) W2)[n])
__device__ __half d_W1h[64 * 128];
__device__ __half d_W2h[128 * 64];
__device__ __half d_fcW1h[128 * 128];
__device__ __half d_fcW2h[128 * 64];
__device__ int    d_counts[NN];
__device__ int    d_rowstart[NN];
__device__ int    d_cursor[NN];
__device__ float  d_dinv[NN];
__device__ int    d_csrsrc[EE];
__device__ int    d_bsum[256];

// ------------- init: zero counts + convert all weights to fp16 -------------
__global__ void k_init(const float* __restrict__ W1, const float* __restrict__ W2,
                       const float* __restrict__ fcW1, const float* __restrict__ fcW2) {
    int i = blockIdx.x * blockDim.x + threadIdx.x;
    if (i < NN) d_counts[i] = 0;
    if (i < 8192)       d_W1h[i]        = __float2half(W1[i]);
    else if (i < 16384) d_W2h[i - 8192] = __float2half(W2[i - 8192]);
    if (i < 16384)      d_fcW1h[i]          = __float2half(fcW1[i]);
    else if (i < 24576) d_fcW2h[i - 16384]  = __float2half(fcW2[i - 16384]);
}

__global__ void k_count(const int* __restrict__ dst) {
    int e = blockIdx.x * blockDim.x + threadIdx.x;
    if (e < EE) atomicAdd(&d_counts[dst[e]], 1);
}

// block-level exclusive scan via warp shuffles (1024 threads = 32 warps)
__global__ void k_scan1() {
    __shared__ int wsum[32];
    int t = threadIdx.x;
    int i = blockIdx.x * 1024 + t;
    int v = (i < NN) ? d_counts[i] : 0;
    int lane = t & 31, w = t >> 5;
    int x = v;
    #pragma unroll
    for (int o = 1; o < 32; o <<= 1) {
        int y = __shfl_up_sync(0xffffffffu, x, o);
        if (lane >= o) x += y;
    }
    if (lane == 31) wsum[w] = x;
    __syncthreads();
    if (w == 0) {
        int s = wsum[lane];
        #pragma unroll
        for (int o = 1; o < 32; o <<= 1) {
            int y = __shfl_up_sync(0xffffffffu, s, o);
            if (lane >= o) s += y;
        }
        wsum[lane] = s;
    }
    __syncthreads();
    int incl = x + ((w > 0) ? wsum[w - 1] : 0);
    if (i < NN) d_rowstart[i] = incl - v;
    if (t == 1023) d_bsum[blockIdx.x] = incl;
}

// scan3: cross-block prefix + finalize rowstart/cursor/dinv + FUSED prescale
__global__ void k_scan3(const float* __restrict__ x) {
    __shared__ int pref;
    __shared__ float sdinv[1024];
    int b = blockIdx.x, t = threadIdx.x;
    if (t < 32) {
        int s = 0;
        for (int j = t; j < b; j += 32) s += d_bsum[j];
        #pragma unroll
        for (int o = 16; o; o >>= 1)
            s += __shfl_xor_sync(0xffffffffu, s, o);
        if (t == 0) pref = s;
    }
    __syncthreads();
    int i = b * 1024 + t;
    float di = 0.f;
    if (i < NN) {
        int rs = d_rowstart[i] + pref;
        d_rowstart[i] = rs;
        d_cursor[i]   = rs;
        di = rsqrtf(1.0f + (float)d_counts[i]);
        d_dinv[i] = di;
    }
    sdinv[t] = di;
    __syncthreads();
    int nb = b * 1024;
    for (int e = t; e < 1024 * 32; e += 1024) {
        int node = nb + (e >> 5);
        if (node < NN) {
            float2 v = ((const float2*)x)[(size_t)node * 32 + (e & 31)];
            float d = sdinv[e >> 5];
            ((__half2*)d_xs)[(size_t)node * 32 + (e & 31)] =
                __floats2half2_rn(v.x * d, v.y * d);
        }
    }
}

__global__ void k_fill(const int* __restrict__ src, const int* __restrict__ dst) {
    int e = blockIdx.x * blockDim.x + threadIdx.x;
    if (e < EE) {
        int d = dst[e];
        int p = atomicAdd(&d_cursor[d], 1);
        d_csrsrc[p] = src[e];
    }
}

// ---------------- aggregation layer 1 (F=64, warp per node) ----------------
__global__ void k_agg1() {
    int gw   = (blockIdx.x * blockDim.x + threadIdx.x) >> 5;
    int lane = threadIdx.x & 31;
    if (gw >= NN) return;
    int rs  = d_rowstart[gw];
    int cnt = d_counts[gw];
    const __half2* base = (const __half2*)d_xs;
    float2 self = __half22float2(base[(size_t)gw * 32 + lane]);
    float ax = self.x, ay = self.y;
    #pragma unroll 4
    for (int j = 0; j < cnt; j++) {
        int s = __ldg(&d_csrsrc[rs + j]);
        float2 v = __half22float2(base[(size_t)s * 32 + lane]);
        ax += v.x; ay += v.y;
    }
    float di = d_dinv[gw];
    ((__half2*)d_ax)[(size_t)gw * 32 + lane] = __floats2half2_rn(di * ax, di * ay);
}

// ---- fused GEMM (wmma): xs2 = fp16(dinv * (relu(ax@W1 + b1) @ W2)) --------
// 64-row tile. smem pool 48KB with aliasing:
//   [0,8K)    As: ax tile 64x64 fp16       (phase-1 A; dead after MMA1)
//   [8K,24K)  Bs: W1 64x128, then W2 128x64 fp16
//   [24K,40K) Hs: h1 tile 64x128 fp16
//   [0,9.25K) St: per-warp fp32 staging 8x16x18 (aliases As + head of Bs;
//             only live in epilogues, when those regions are dead)
__global__ __launch_bounds__(256) void k_gemm_fused(const float* __restrict__ b1) {
    __shared__ __align__(16) char pool[49152];
    __half* As = (__half*)pool;
    __half* Bs = (__half*)(pool + 8192);
    __half* Hs = (__half*)(pool + 24576);
    int t = threadIdx.x;
    int rowbase = blockIdx.x * 64;
    int w  = t >> 5, lane = t & 31;
    int wr = w >> 1;           // row group 0..3
    int wc = w & 1;            // col group 0..1
    float* St = (float*)pool + w * 288;   // 16x18 floats per warp

    // ---- load ax tile + W1 ----
    for (int i = t; i < 64 * 32; i += 256) {
        int row = rowbase + (i >> 5);
        ((__half2*)As)[i] = (row < NN) ? ((const __half2*)d_ax)[(size_t)rowbase * 32 + i]
                                       : __floats2half2_rn(0.f, 0.f);
    }
    for (int i = t; i < 4096; i += 256)
        ((__half2*)Bs)[i] = ((const __half2*)d_W1h)[i];
    __syncthreads();

    // ---- MMA phase 1: h1 = ax @ W1 ----
    wmma::fragment<wmma::accumulator, 16, 16, 16, float> cf[4];
    #pragma unroll
    for (int j = 0; j < 4; j++) wmma::fill_fragment(cf[j], 0.0f);
    #pragma unroll
    for (int k = 0; k < 4; k++) {
        wmma::fragment<wmma::matrix_a, 16, 16, 16, __half, wmma::row_major> af;
        wmma::load_matrix_sync(af, As + (wr * 16) * 64 + k * 16, 64);
        #pragma unroll
        for (int j = 0; j < 4; j++) {
            wmma::fragment<wmma::matrix_b, 16, 16, 16, __half, wmma::row_major> bf;
            wmma::load_matrix_sync(bf, Bs + (k * 16) * 128 + wc * 64 + j * 16, 128);
            wmma::mma_sync(cf[j], af, bf, cf[j]);
        }
    }
    __syncthreads();   // As/Bs reads done -> St may alias them

    // ---- epilogue 1: bias + relu -> Hs (fp16) ----
    #pragma unroll
    for (int j = 0; j < 4; j++) {
        wmma::store_matrix_sync(St, cf[j], 18, wmma::mem_row_major);
        __syncwarp();
        int colbase = wc * 64 + j * 16;
        for (int i = lane; i < 128; i += 32) {     // 16 rows x 8 half2
            int lr = i >> 3, c2 = (i & 7) * 2;
            float v0 = fmaxf(St[lr * 18 + c2]     + b1[colbase + c2], 0.f);
            float v1 = fmaxf(St[lr * 18 + c2 + 1] + b1[colbase + c2 + 1], 0.f);
            ((__half2*)Hs)[(wr * 16 + lr) * 64 + (colbase >> 1) + (i & 7)] =
                __floats2half2_rn(v0, v1);
        }
        __syncwarp();
    }
    __syncthreads();   // St dead; Hs complete

    // ---- load W2 (overwrites W1 region + St tail) ----
    for (int i = t; i < 4096; i += 256)
        ((__half2*)Bs)[i] = ((const __half2*)d_W2h)[i];
    __syncthreads();

    // ---- MMA phase 2: xs2 = h1 @ W2 ----
    wmma::fragment<wmma::accumulator, 16, 16, 16, float> cf2[2];
    #pragma unroll
    for (int j = 0; j < 2; j++) wmma::fill_fragment(cf2[j], 0.0f);
    #pragma unroll
    for (int k = 0; k < 8; k++) {
        wmma::fragment<wmma::matrix_a, 16, 16, 16, __half, wmma::row_major> af;
        wmma::load_matrix_sync(af, Hs + (wr * 16) * 128 + k * 16, 128);
        #pragma unroll
        for (int j = 0; j < 2; j++) {
            wmma::fragment<wmma::matrix_b, 16, 16, 16, __half, wmma::row_major> bf;
            wmma::load_matrix_sync(bf, Bs + (k * 16) * 64 + wc * 32 + j * 16, 64);
            wmma::mma_sync(cf2[j], af, bf, cf2[j]);
        }
    }
    __syncthreads();   // Hs/Bs reads done -> St reuse safe

    // ---- epilogue 2: dinv scale -> d_xs2 (fp16 global) ----
    #pragma unroll
    for (int j = 0; j < 2; j++) {
        wmma::store_matrix_sync(St, cf2[j], 18, wmma::mem_row_major);
        __syncwarp();
        int colbase = wc * 32 + j * 16;
        for (int i = lane; i < 128; i += 32) {
            int lr = i >> 3, c2 = (i & 7) * 2;
            int row = rowbase + wr * 16 + lr;
            if (row < NN) {
                float di = d_dinv[row];
                float v0 = di * St[lr * 18 + c2];
                float v1 = di * St[lr * 18 + c2 + 1];
                ((__half2*)d_xs2)[(size_t)row * 32 + (colbase >> 1) + (i & 7)] =
                    __floats2half2_rn(v0, v1);
            }
        }
        __syncwarp();
    }
}

// ------ fused layer-2 agg + MLP head: 8 rows/block, fp16 weights ------------
__global__ __launch_bounds__(256) void k_mlp(
        const int* __restrict__ ui, const int* __restrict__ ii,
        const float* __restrict__ b2,
        const float* __restrict__ fcb1,
        const float* __restrict__ g1,   const float* __restrict__ be1,
        const float* __restrict__ fcb2,
        const float* __restrict__ g2,   const float* __restrict__ be2,
        const float* __restrict__ fcW3, const float* __restrict__ fcb3,
        float* __restrict__ out) {
    __shared__ float cs[8][128];
    __shared__ float zs[8][128];
    __shared__ float rS[8][2], rQ[8][2];
    int t = threadIdx.x, lane = t & 31, w = t >> 5;
    int r0 = blockIdx.x * 8;

    {
        int row = r0 + w;
        const __half2* base = (const __half2*)d_xs2;
        float2 bv = ((const float2*)b2)[lane];
        #pragma unroll
        for (int half = 0; half < 2; half++) {
            int node = (half == 0) ? (ui[row] - 1) : (ii[row] - 1 + N_USERS);
            int rs  = d_rowstart[node];
            int cnt = d_counts[node];
            float2 self = __half22float2(base[(size_t)node * 32 + lane]);
            float ax = self.x, ay = self.y;
            #pragma unroll 4
            for (int j = 0; j < cnt; j++) {
                int s = __ldg(&d_csrsrc[rs + j]);
                float2 v = __half22float2(base[(size_t)s * 32 + lane]);
                ax += v.x; ay += v.y;
            }
            float di = d_dinv[node];
            cs[w][half * 64 + lane * 2]     = di * ax + bv.x;
            cs[w][half * 64 + lane * 2 + 1] = di * ay + bv.y;
        }
    }
    __syncthreads();

    int c2 = t & 63;
    int g  = t >> 6;
    int wg = w & 1;
    const __half2* W1h = (const __half2*)d_fcW1h;
    float2 b1v = ((const float2*)fcb1)[c2];
    float a0x = b1v.x, a0y = b1v.y, a1x = b1v.x, a1y = b1v.y;
    #pragma unroll 8
    for (int k = 0; k < 128; k++) {
        float2 wv = __half22float2(W1h[k * 64 + c2]);
        float v0 = cs[2 * g][k], v1 = cs[2 * g + 1][k];
        a0x = fmaf(v0, wv.x, a0x); a0y = fmaf(v0, wv.y, a0y);
        a1x = fmaf(v1, wv.x, a1x); a1y = fmaf(v1, wv.y, a1y);
    }
    float s0 = a0x + a0y, q0 = a0x * a0x + a0y * a0y;
    float s1 = a1x + a1y, q1 = a1x * a1x + a1y * a1y;
    #pragma unroll
    for (int o = 16; o; o >>= 1) {
        s0 += __shfl_xor_sync(0xffffffffu, s0, o);
        q0 += __shfl_xor_sync(0xffffffffu, q0, o);
        s1 += __shfl_xor_sync(0xffffffffu, s1, o);
        q1 += __shfl_xor_sync(0xffffffffu, q1, o);
    }
    if (lane == 0) {
        rS[2 * g][wg] = s0; rQ[2 * g][wg] = q0;
        rS[2 * g + 1][wg] = s1; rQ[2 * g + 1][wg] = q1;
    }
    __syncthreads();
    {
        float2 g1v = ((const float2*)g1)[c2];
        float2 be1v = ((const float2*)be1)[c2];
        float S0 = rS[2 * g][0] + rS[2 * g][1];
        float Q0 = rQ[2 * g][0] + rQ[2 * g][1];
        float S1 = rS[2 * g + 1][0] + rS[2 * g + 1][1];
        float Q1 = rQ[2 * g + 1][0] + rQ[2 * g + 1][1];
        float m0 = S0 * (1.f / 128.f), v0 = Q0 * (1.f / 128.f) - m0 * m0;
        float m1 = S1 * (1.f / 128.f), v1 = Q1 * (1.f / 128.f) - m1 * m1;
        float r0s = rsqrtf(v0 + LN_EPS), r1s = rsqrtf(v1 + LN_EPS);
        float z0x = fmaxf((a0x - m0) * r0s * g1v.x + be1v.x, 0.f);
        float z0y = fmaxf((a0y - m0) * r0s * g1v.y + be1v.y, 0.f);
        float z1x = fmaxf((a1x - m1) * r1s * g1v.x + be1v.x, 0.f);
        float z1y = fmaxf((a1y - m1) * r1s * g1v.y + be1v.y, 0.f);
        ((float2*)zs[2 * g])[c2]     = make_float2(z0x, z0y);
        ((float2*)zs[2 * g + 1])[c2] = make_float2(z1x, z1y);
    }
    __syncthreads();

    {
        const __half2* W2h = (const __half2*)d_fcW2h;
        float2 b2v = ((const float2*)fcb2)[lane];
        float ax = b2v.x, ay = b2v.y;
        #pragma unroll 8
        for (int k = 0; k < 128; k++) {
            float2 wv = __half22float2(W2h[k * 32 + lane]);
            float v = zs[w][k];
            ax = fmaf(v, wv.x, ax); ay = fmaf(v, wv.y, ay);
        }
        float a = ax + ay, q = ax * ax + ay * ay;
        #pragma unroll
        for (int o = 16; o; o >>= 1) {
            a += __shfl_xor_sync(0xffffffffu, a, o);
            q += __shfl_xor_sync(0xffffffffu, q, o);
        }
        float mean = a * (1.f / 64.f);
        float var  = q * (1.f / 64.f) - mean * mean;
        float rstd = rsqrtf(var + LN_EPS);
        float2 g2v = ((const float2*)g2)[lane];
        float2 be2v = ((const float2*)be2)[lane];
        float2 w3v = ((const float2*)fcW3)[lane];
        float z0 = fmaxf((ax - mean) * rstd * g2v.x + be2v.x, 0.f);
        float z1 = fmaxf((ay - mean) * rstd * g2v.y + be2v.y, 0.f);
        float p = z0 * w3v.x + z1 * w3v.y;
        #pragma unroll
        for (int o = 16; o; o >>= 1)
            p += __shfl_xor_sync(0xffffffffu, p, o);
        if (lane == 0)
            out[r0 + w] = 1.0f / (1.0f + expf(-(p + fcb3[0])));
    }
}

// ---------------- launch ----------------
extern "C" void kernel_launch(void* const* d_in, const int* in_sizes, int n_in,
                              void* d_out, int out_size) {
    const float* x    = (const float*)d_in[0];
    const int*   src  = (const int*)  d_in[1];
    const int*   dst  = (const int*)  d_in[2];
    const int*   uidx = (const int*)  d_in[3];
    const int*   iidx = (const int*)  d_in[4];
    const float* W1   = (const float*)d_in[5];
    const float* b1   = (const float*)d_in[6];
    const float* W2   = (const float*)d_in[7];
    const float* b2   = (const float*)d_in[8];
    const float* fcW1 = (const float*)d_in[9];
    const float* fcb1 = (const float*)d_in[10];
    const float* g1   = (const float*)d_in[11];
    const float* be1  = (const float*)d_in[12];
    const float* fcW2 = (const float*)d_in[13];
    const float* fcb2 = (const float*)d_in[14];
    const float* g2   = (const float*)d_in[15];
    const float* be2  = (const float*)d_in[16];
    const float* fcW3 = (const float*)d_in[17];
    const float* fcb3 = (const float*)d_in[18];
    float* out = (float*)d_out;

    // CSR build (+ weight conversion, + fused prescale in scan3)
    k_init<<<(NN + 255) / 256, 256>>>(W1, W2, fcW1, fcW2);
    k_count<<<(EE + 255) / 256, 256>>>(dst);
    k_scan1<<<NBLKS, 1024>>>();
    k_scan3<<<NBLKS, 1024>>>(x);
    k_fill<<<(EE + 255) / 256, 256>>>(src, dst);

    // layer 1 aggregate (fp16 gathers), then fused tensor-core 64->128->64
    k_agg1<<<(NN * 32 + 255) / 256, 256>>>();
    k_gemm_fused<<<(NN + 63) / 64, 256>>>(b1);

    // fused agg2 + MLP head (8 pairs per block, fp16 weights)
    k_mlp<<<BB / 8, 256>>>(uidx, iidx, b2, fcb1, g1, be1,
                           fcb2, g2, be2, fcW3, fcb3, out);
}